// round 2
// baseline (speedup 1.0000x reference)
#include <cuda_runtime.h>
#include <math.h>

// Problem dims
#define Ln 512
#define Nn 256
#define DMSA 256
#define DPAIR 128
#define Hh 8
#define Dd 32
#define HD 256
#define NL (Nn*Ln)          // 131072
#define ND (Nn*Dd)          // 8192
#define SCALING 0.17677669529663689f
#define EPSC 1e-5f

// Scratch (device globals: allocation-free rule).
// g_buf0 is msa_n for the first half of the pipeline, then reused as the
// gated attention output 'o' (msa_n's last reader = k_gemm_qkvg; o's first
// writer = k_gemm_av).
__device__ float g_buf0[NL*DMSA];       // msa_n [r=(n,l)][c]  /  o [h][q][n*32+d]
__device__ float g_gate [NL*HD];        // [r][h*32+d]
__device__ float g_qs[Hh*Ln*ND];        // [h][l][n*32+d]
__device__ float g_ks[Hh*Ln*ND];
__device__ float g_vs[Hh*Ln*ND];
__device__ float g_attn[Hh*Ln*Ln];      // [h][q][k]
__device__ float g_bias[Ln*Ln*Hh];      // [q][k][h]

__device__ __forceinline__ float fixf(float v){
    if (isnan(v)) return 0.f;
    if (isinf(v)) return v > 0.f ? 3.4028234663852886e38f : -3.4028234663852886e38f;
    return v;
}

// ---------------- LayerNorm msa ----------------
__global__ void k_ln_msa(const float* __restrict__ msa,
                         const float* __restrict__ g,
                         const float* __restrict__ b){
    int warp = threadIdx.x >> 5, lane = threadIdx.x & 31;
    size_t row = (size_t)blockIdx.x * 8 + warp;
    const float* x = msa + row * DMSA;
    float v[8]; float s = 0.f;
    #pragma unroll
    for (int i = 0; i < 8; i++){ float t = fixf(x[lane + i*32]); v[i] = t; s += t; }
    #pragma unroll
    for (int o = 16; o; o >>= 1) s += __shfl_xor_sync(0xffffffffu, s, o);
    float mu = s * (1.f/256.f);
    float q = 0.f;
    #pragma unroll
    for (int i = 0; i < 8; i++){ float d0 = v[i] - mu; q += d0*d0; }
    #pragma unroll
    for (int o = 16; o; o >>= 1) q += __shfl_xor_sync(0xffffffffu, q, o);
    float rs = rsqrtf(q * (1.f/256.f) + EPSC);
    float* o = g_buf0 + row * DMSA;
    #pragma unroll
    for (int i = 0; i < 8; i++){
        int c = lane + i*32;
        o[c] = (v[i] - mu) * rs * g[c] + b[c];
    }
}

// ---------------- LayerNorm pair + bias GEMV (K=128, 8 outputs) ----------------
__global__ void k_pair_bias(const float* __restrict__ pair,
                            const float* __restrict__ g,
                            const float* __restrict__ b,
                            const float* __restrict__ wb){
    __shared__ float swb[Hh*DPAIR];   // transposed: [h][c]
    for (int i = threadIdx.x; i < Hh*DPAIR; i += blockDim.x){
        int h = i / DPAIR, c = i % DPAIR;
        swb[i] = wb[c*Hh + h];
    }
    __syncthreads();
    int warp = threadIdx.x >> 5, lane = threadIdx.x & 31;
    size_t row = (size_t)blockIdx.x * 8 + warp;   // (q,k) flat, < 262144
    const float* x = pair + row * DPAIR;
    float v[4]; float s = 0.f;
    #pragma unroll
    for (int i = 0; i < 4; i++){ float t = fixf(x[lane + i*32]); v[i] = t; s += t; }
    #pragma unroll
    for (int o = 16; o; o >>= 1) s += __shfl_xor_sync(0xffffffffu, s, o);
    float mu = s * (1.f/128.f);
    float q = 0.f;
    #pragma unroll
    for (int i = 0; i < 4; i++){ float d0 = v[i] - mu; q += d0*d0; }
    #pragma unroll
    for (int o = 16; o; o >>= 1) q += __shfl_xor_sync(0xffffffffu, q, o);
    float rs = rsqrtf(q * (1.f/128.f) + EPSC);
    float acc[8] = {0.f,0.f,0.f,0.f,0.f,0.f,0.f,0.f};
    #pragma unroll
    for (int i = 0; i < 4; i++){
        int c = lane + i*32;
        float pn = (v[i] - mu) * rs * g[c] + b[c];
        #pragma unroll
        for (int h = 0; h < 8; h++) acc[h] += pn * swb[h*DPAIR + c];
    }
    #pragma unroll
    for (int h = 0; h < 8; h++)
        #pragma unroll
        for (int o = 16; o; o >>= 1) acc[h] += __shfl_xor_sync(0xffffffffu, acc[h], o);
    float outv = 0.f;
    #pragma unroll
    for (int h = 0; h < 8; h++) if (lane == h) outv = acc[h];
    if (lane < 8) g_bias[row*Hh + lane] = outv;
}

// ---------------- GEMM core: BM=128 BN=64 BK=16, 256 thr, 8x4 per thread ----------------
#define AST 132
#define BST 68

__device__ __forceinline__ void mm_core(const float* As, const float* Bs,
                                        float acc[8][4], int ty, int tx){
    #pragma unroll
    for (int kk = 0; kk < 16; kk++){
        float a[8], b[4];
        #pragma unroll
        for (int i = 0; i < 8; i++) a[i] = As[kk*AST + ty*8 + i];
        #pragma unroll
        for (int j = 0; j < 4; j++) b[j] = Bs[kk*BST + tx*4 + j];
        #pragma unroll
        for (int i = 0; i < 8; i++)
            #pragma unroll
            for (int j = 0; j < 4; j++) acc[i][j] += a[i]*b[j];
    }
}

__device__ __forceinline__ void load_a_tile(float* As, const float* A, int lda,
                                            int m0, int kt, int tid){
    #pragma unroll
    for (int p = 0; p < 2; p++){
        int r = p*64 + (tid >> 2);
        int c = (tid & 3)*4;
        float4 v = *(const float4*)(A + (size_t)(m0+r)*lda + kt + c);
        As[(c+0)*AST + r] = v.x; As[(c+1)*AST + r] = v.y;
        As[(c+2)*AST + r] = v.z; As[(c+3)*AST + r] = v.w;
    }
}
// B row-major [N,K], staged transposed (NT gemm)
__device__ __forceinline__ void load_bt_tile(float* Bs, const float* B, int ldb,
                                             int n0, int kt, int tid){
    int r = tid >> 2;          // 0..63
    int c = (tid & 3)*4;
    float4 v = *(const float4*)(B + (size_t)(n0+r)*ldb + kt + c);
    Bs[(c+0)*BST + r] = v.x; Bs[(c+1)*BST + r] = v.y;
    Bs[(c+2)*BST + r] = v.z; Bs[(c+3)*BST + r] = v.w;
}
// B row-major [K,N] (NN gemm)
__device__ __forceinline__ void load_bn_tile(float* Bs, const float* B, int ldb,
                                             int kt, int n0, int tid){
    int r = tid >> 4;          // 0..15
    int c = (tid & 15)*4;
    float4 v = *(const float4*)(B + (size_t)(kt+r)*ldb + n0 + c);
    *(float4*)(Bs + r*BST + c) = v;
}

// ---------------- QKVG: msa_n[131072x256] @ W[256x256], z selects q/k/v/g ----------------
__global__ void k_gemm_qkvg(const float* __restrict__ wq, const float* __restrict__ wk,
                            const float* __restrict__ wv, const float* __restrict__ wg,
                            const float* __restrict__ bg, const int* __restrict__ mask){
    __shared__ float As[16*AST];
    __shared__ float Bs[16*BST];
    int tid = threadIdx.x, tx = tid & 15, ty = tid >> 4;
    int z = blockIdx.z;
    const float* B = (z==0) ? wq : (z==1) ? wk : (z==2) ? wv : wg;
    int m0 = blockIdx.y * 128, n0 = blockIdx.x * 64;
    float acc[8][4] = {};
    for (int kt = 0; kt < 256; kt += 16){
        load_a_tile(As, g_buf0, 256, m0, kt, tid);
        load_bn_tile(Bs, B, 256, kt, n0, tid);
        __syncthreads();
        mm_core(As, Bs, acc, ty, tx);
        __syncthreads();
    }
    #pragma unroll
    for (int i = 0; i < 8; i++){
        int r = m0 + ty*8 + i;
        int l = r & (Ln-1);
        int n = r >> 9;
        bool pad = (mask[l] == 0);
        #pragma unroll
        for (int j = 0; j < 4; j++){
            int col = n0 + tx*4 + j;
            float v = acc[i][j];
            if (z == 3){
                v = 1.f/(1.f + expf(-(v + bg[col])));
                g_gate[(size_t)r*HD + col] = v;
            } else {
                if (pad) v = 0.f;
                else if (z == 1) v *= SCALING;
                int h = col >> 5, d = col & 31;
                size_t idx = (((size_t)h*Ln + l)*Nn + n)*Dd + d;
                if (z == 0) g_qs[idx] = v;
                else if (z == 1) g_ks[idx] = v;
                else g_vs[idx] = v;
            }
        }
    }
}

// ---------------- attn logits: per head Q[512x8192] @ K^T ----------------
__global__ void k_gemm_attn(){
    __shared__ float As[16*AST];
    __shared__ float Bs[16*BST];
    int tid = threadIdx.x, tx = tid & 15, ty = tid >> 4;
    int h = blockIdx.z;
    const float* A = g_qs + (size_t)h*Ln*ND;
    const float* B = g_ks + (size_t)h*Ln*ND;
    int m0 = blockIdx.y * 128, n0 = blockIdx.x * 64;
    float acc[8][4] = {};
    for (int kt = 0; kt < ND; kt += 16){
        load_a_tile(As, A, ND, m0, kt, tid);
        load_bt_tile(Bs, B, ND, n0, kt, tid);
        __syncthreads();
        mm_core(As, Bs, acc, ty, tx);
        __syncthreads();
    }
    float* C = g_attn + (size_t)h*Ln*Ln;
    #pragma unroll
    for (int i = 0; i < 8; i++)
        #pragma unroll
        for (int j = 0; j < 4; j++)
            C[(size_t)(m0 + ty*8 + i)*Ln + n0 + tx*4 + j] = acc[i][j];
}

// ---------------- softmax over k with bias + mask ----------------
__global__ void k_softmax(const int* __restrict__ mask){
    int h = blockIdx.x >> 9, q = blockIdx.x & (Ln-1);
    float* row = g_attn + ((size_t)h*Ln + q)*Ln;
    bool padq = (mask[q] == 0);
    int t = threadIdx.x;
    int k0 = t, k1 = t + 256;
    float v0 = (padq || mask[k0] == 0) ? -1e9f : row[k0] + g_bias[((size_t)q*Ln + k0)*Hh + h];
    float v1 = (padq || mask[k1] == 0) ? -1e9f : row[k1] + g_bias[((size_t)q*Ln + k1)*Hh + h];
    __shared__ float red[256];
    red[t] = fmaxf(v0, v1); __syncthreads();
    for (int s = 128; s > 0; s >>= 1){ if (t < s) red[t] = fmaxf(red[t], red[t+s]); __syncthreads(); }
    float m = red[0]; __syncthreads();
    float e0 = expf(v0 - m), e1 = expf(v1 - m);
    red[t] = e0 + e1; __syncthreads();
    for (int s = 128; s > 0; s >>= 1){ if (t < s) red[t] += red[t+s]; __syncthreads(); }
    float inv = 1.f / red[0];
    row[k0] = e0*inv; row[k1] = e1*inv;
}

// ---------------- AV: per head P[512x512] @ V[512x8192], gate fused ----------------
__global__ void k_gemm_av(){
    __shared__ float As[16*AST];
    __shared__ float Bs[16*BST];
    int tid = threadIdx.x, tx = tid & 15, ty = tid >> 4;
    int h = blockIdx.z;
    const float* A = g_attn + (size_t)h*Ln*Ln;
    const float* B = g_vs   + (size_t)h*Ln*ND;
    int m0 = blockIdx.y * 128, n0 = blockIdx.x * 64;
    float acc[8][4] = {};
    for (int kt = 0; kt < Ln; kt += 16){
        load_a_tile(As, A, Ln, m0, kt, tid);
        load_bn_tile(Bs, B, ND, kt, n0, tid);
        __syncthreads();
        mm_core(As, Bs, acc, ty, tx);
        __syncthreads();
    }
    float* C = g_buf0 + (size_t)h*Ln*ND;   // o  [h][q][n*32+d]
    #pragma unroll
    for (int i = 0; i < 8; i++){
        int q = m0 + ty*8 + i;
        #pragma unroll
        for (int j = 0; j < 4; j++){
            int col = n0 + tx*4 + j;
            int n = col >> 5, d = col & 31;
            float gate = g_gate[((size_t)n*Ln + q)*HD + h*Dd + d];
            C[(size_t)q*ND + col] = acc[i][j] * gate;
        }
    }
}

// ---------------- out = gather(o)[131072x256] @ w_out + b_out, pad->0 ----------------
__global__ void k_gemm_final(const float* __restrict__ wout, const float* __restrict__ bout,
                             const int* __restrict__ mask, float* __restrict__ out){
    __shared__ float As[16*AST];
    __shared__ float Bs[16*BST];
    int tid = threadIdx.x, tx = tid & 15, ty = tid >> 4;
    int m0 = blockIdx.y * 128, n0 = blockIdx.x * 64;
    float acc[8][4] = {};
    for (int kt = 0; kt < 256; kt += 16){
        // A[r, c] = o[h=c>>5][l=r&511][n=r>>9, d=c&31]
        #pragma unroll
        for (int p = 0; p < 2; p++){
            int rl = p*64 + (tid >> 2);
            int c  = (tid & 3)*4;
            int r  = m0 + rl;
            int n  = r >> 9, l = r & (Ln-1);
            int cc = kt + c;
            int hh = cc >> 5, dd = cc & 31;
            float4 v = *(const float4*)(g_buf0 + ((size_t)hh*Ln + l)*ND + n*Dd + dd);
            As[(c+0)*AST + rl] = v.x; As[(c+1)*AST + rl] = v.y;
            As[(c+2)*AST + rl] = v.z; As[(c+3)*AST + rl] = v.w;
        }
        load_bn_tile(Bs, wout, 256, kt, n0, tid);
        __syncthreads();
        mm_core(As, Bs, acc, ty, tx);
        __syncthreads();
    }
    #pragma unroll
    for (int i = 0; i < 8; i++){
        int r = m0 + ty*8 + i;
        int l = r & (Ln-1);
        bool pad = (mask[l] == 0);
        #pragma unroll
        for (int j = 0; j < 4; j++){
            int col = n0 + tx*4 + j;
            float v = acc[i][j] + bout[col];
            if (pad) v = 0.f;
            out[(size_t)r*HD + col] = v;
        }
    }
}

extern "C" void kernel_launch(void* const* d_in, const int* in_sizes, int n_in,
                              void* d_out, int out_size){
    const float* msa      = (const float*)d_in[0];
    const float* pair     = (const float*)d_in[1];
    const float* ln_msa_g = (const float*)d_in[2];
    const float* ln_msa_b = (const float*)d_in[3];
    const float* ln_pr_g  = (const float*)d_in[4];
    const float* ln_pr_b  = (const float*)d_in[5];
    const float* w_q      = (const float*)d_in[6];
    const float* w_k      = (const float*)d_in[7];
    const float* w_v      = (const float*)d_in[8];
    const float* w_b      = (const float*)d_in[9];
    const float* w_g      = (const float*)d_in[10];
    const float* b_g      = (const float*)d_in[11];
    const float* w_out    = (const float*)d_in[12];
    const float* b_out    = (const float*)d_in[13];
    const int*   mask     = (const int*)  d_in[14];
    float* out = (float*)d_out;

    k_ln_msa   <<<NL/8, 256>>>(msa, ln_msa_g, ln_msa_b);
    k_pair_bias<<<(Ln*Ln)/8, 256>>>(pair, ln_pr_g, ln_pr_b, w_b);
    k_gemm_qkvg<<<dim3(4, NL/128, 4), 256>>>(w_q, w_k, w_v, w_g, b_g, mask);
    k_gemm_attn<<<dim3(Ln/64, Ln/128, Hh), 256>>>();
    k_softmax  <<<Hh*Ln, 256>>>(mask);
    k_gemm_av  <<<dim3(ND/64, Ln/128, Hh), 256>>>();
    k_gemm_final<<<dim3(4, NL/128), 256>>>(w_out, b_out, mask, out);
}

// round 7
// speedup vs baseline: 1.7174x; 1.7174x over previous
#include <cuda_runtime.h>
#include <cuda_bf16.h>
#include <stdint.h>
#include <math.h>

// Problem dims
#define Ln 512
#define Nn 256
#define DMSA 256
#define DPAIR 128
#define Hh 8
#define Dd 32
#define HD 256
#define NL (Nn*Ln)          // 131072
#define NDIM 8192           // (n,d) contraction dim
#define SCALING 0.17677669529663689f
#define EPSC 1e-5f

typedef __nv_bfloat16 bf16;

// ----------------------------------------------------------------------------
// Scratch (device globals). Aliasing:
//   g_bufA = msa_n (hi/lo)  then  v^T (hi/lo)
//   g_bufB = q (hi/lo)      then  o (hi/lo)
__device__ __align__(16) bf16 g_bufA_hi[33554432];
__device__ __align__(16) bf16 g_bufA_lo[33554432];
__device__ __align__(16) bf16 g_bufB_hi[33554432];
__device__ __align__(16) bf16 g_bufB_lo[33554432];
__device__ __align__(16) bf16 g_k_hi[33554432];   // [h][l][nd]
__device__ __align__(16) bf16 g_k_lo[33554432];
__device__ __align__(16) bf16 g_v_hi[33554432];   // [h][l][nd]
__device__ __align__(16) bf16 g_v_lo[33554432];
__device__ __align__(16) bf16 g_p_hi[2097152];    // [h][q][k]
__device__ __align__(16) bf16 g_p_lo[2097152];
__device__ __align__(16) bf16 g_wt_hi[327680];    // [1280][256]
__device__ __align__(16) bf16 g_wt_lo[327680];
__device__ float g_gate[33554432];                // [r=(n,l)][h*32+d]
__device__ float g_attn[2097152];                 // [h][q][k]
__device__ float g_bias[2097152];                 // [q][k][h]

// ----------------------------------------------------------------------------
__device__ __forceinline__ uint32_t s2u(const void* p){
    uint32_t a;
    asm("{ .reg .u64 t; cvta.to.shared.u64 t, %1; cvt.u32.u64 %0, t; }" : "=r"(a) : "l"(p));
    return a;
}
#define CP16(sa, gp) \
    asm volatile("cp.async.cg.shared.global [%0], [%1], 16;" :: "r"(sa), "l"(gp))
#define CPCOMMIT() asm volatile("cp.async.commit_group;" ::: "memory")
#define CPWAIT(n)  asm volatile("cp.async.wait_group %0;" :: "n"(n) : "memory")

__device__ __forceinline__ void ldsm4(uint32_t a, uint32_t r[4]){
    asm volatile("ldmatrix.sync.aligned.m8n8.x4.shared.b16 {%0,%1,%2,%3}, [%4];"
                 : "=r"(r[0]), "=r"(r[1]), "=r"(r[2]), "=r"(r[3]) : "r"(a));
}
__device__ __forceinline__ void mma16816(float c[4], const uint32_t a[4],
                                         uint32_t b0, uint32_t b1){
    asm volatile("mma.sync.aligned.m16n8k16.row.col.f32.bf16.bf16.f32 "
                 "{%0,%1,%2,%3}, {%4,%5,%6,%7}, {%8,%9}, {%0,%1,%2,%3};"
                 : "+f"(c[0]), "+f"(c[1]), "+f"(c[2]), "+f"(c[3])
                 : "r"(a[0]), "r"(a[1]), "r"(a[2]), "r"(a[3]), "r"(b0), "r"(b1));
}
__device__ __forceinline__ void split_store(bf16* hi, bf16* lo, size_t idx, float v){
    bf16 h = __float2bfloat16(v);
    hi[idx] = h;
    lo[idx] = __float2bfloat16(v - __bfloat162float(h));
}
__device__ __forceinline__ float fixf(float v){
    if (isnan(v)) return 0.f;
    if (isinf(v)) return v > 0.f ? 3.4028234663852886e38f : -3.4028234663852886e38f;
    return v;
}

// ----------------------------------------------------------------------------
// LayerNorm msa -> bufA (bf16 hi/lo)
__global__ void k_ln_msa(const float* __restrict__ msa,
                         const float* __restrict__ g,
                         const float* __restrict__ b){
    int warp = threadIdx.x >> 5, lane = threadIdx.x & 31;
    size_t row = (size_t)blockIdx.x * 8 + warp;
    const float* x = msa + row * DMSA;
    float v[8]; float s = 0.f;
    #pragma unroll
    for (int i = 0; i < 8; i++){ float t = fixf(x[lane + i*32]); v[i] = t; s += t; }
    #pragma unroll
    for (int o = 16; o; o >>= 1) s += __shfl_xor_sync(0xffffffffu, s, o);
    float mu = s * (1.f/256.f);
    float q = 0.f;
    #pragma unroll
    for (int i = 0; i < 8; i++){ float d0 = v[i] - mu; q += d0*d0; }
    #pragma unroll
    for (int o = 16; o; o >>= 1) q += __shfl_xor_sync(0xffffffffu, q, o);
    float rs = rsqrtf(q * (1.f/256.f) + EPSC);
    #pragma unroll
    for (int i = 0; i < 8; i++){
        int c = lane + i*32;
        float y = (v[i] - mu) * rs * g[c] + b[c];
        split_store(g_bufA_hi, g_bufA_lo, row*DMSA + c, y);
    }
}

// Weight transpose+split: g_wt[row=(z*256+j)][k] = W_z[k][j]
__global__ void k_conv_w(const float* __restrict__ wq, const float* __restrict__ wk,
                         const float* __restrict__ wv, const float* __restrict__ wg,
                         const float* __restrict__ wo){
    int row = blockIdx.x, kk = threadIdx.x;
    int z = row >> 8, j = row & 255;
    const float* src = (z==0)?wq:(z==1)?wk:(z==2)?wv:(z==3)?wg:wo;
    float v = src[kk*256 + j];
    split_store(g_wt_hi, g_wt_lo, (size_t)row*256 + kk, v);
}

// LayerNorm pair + bias GEMV
__global__ void k_pair_bias(const float* __restrict__ pair,
                            const float* __restrict__ g,
                            const float* __restrict__ b,
                            const float* __restrict__ wb){
    __shared__ float swb[Hh*DPAIR];
    for (int i = threadIdx.x; i < Hh*DPAIR; i += blockDim.x){
        int h = i / DPAIR, c = i % DPAIR;
        swb[i] = wb[c*Hh + h];
    }
    __syncthreads();
    int warp = threadIdx.x >> 5, lane = threadIdx.x & 31;
    size_t row = (size_t)blockIdx.x * 8 + warp;
    const float* x = pair + row * DPAIR;
    float v[4]; float s = 0.f;
    #pragma unroll
    for (int i = 0; i < 4; i++){ float t = fixf(x[lane + i*32]); v[i] = t; s += t; }
    #pragma unroll
    for (int o = 16; o; o >>= 1) s += __shfl_xor_sync(0xffffffffu, s, o);
    float mu = s * (1.f/128.f);
    float q = 0.f;
    #pragma unroll
    for (int i = 0; i < 4; i++){ float d0 = v[i] - mu; q += d0*d0; }
    #pragma unroll
    for (int o = 16; o; o >>= 1) q += __shfl_xor_sync(0xffffffffu, q, o);
    float rs = rsqrtf(q * (1.f/128.f) + EPSC);
    float acc[8] = {};
    #pragma unroll
    for (int i = 0; i < 4; i++){
        int c = lane + i*32;
        float pn = (v[i] - mu) * rs * g[c] + b[c];
        #pragma unroll
        for (int h = 0; h < 8; h++) acc[h] += pn * swb[h*DPAIR + c];
    }
    #pragma unroll
    for (int h = 0; h < 8; h++)
        #pragma unroll
        for (int o = 16; o; o >>= 1) acc[h] += __shfl_xor_sync(0xffffffffu, acc[h], o);
    float outv = 0.f;
    #pragma unroll
    for (int h = 0; h < 8; h++) if (lane == h) outv = acc[h];
    if (lane < 8) g_bias[row*Hh + lane] = outv;
}

// Transpose V: [h][l][nd] -> [h][nd][l] into bufA
__global__ void k_transpose_v(){
    __shared__ bf16 tile[32][33];
    int head = blockIdx.z >> 1, arr = blockIdx.z & 1;
    const bf16* src = (arr ? g_v_lo : g_v_hi) + (size_t)head * Ln * NDIM;
    bf16* dst = (arr ? g_bufA_lo : g_bufA_hi) + (size_t)head * NDIM * Ln;
    int nd0 = blockIdx.x * 32, l0 = blockIdx.y * 32;
    #pragma unroll
    for (int yy = 0; yy < 4; yy++)
        tile[threadIdx.y + yy*8][threadIdx.x] =
            src[(size_t)(l0 + threadIdx.y + yy*8) * NDIM + nd0 + threadIdx.x];
    __syncthreads();
    #pragma unroll
    for (int yy = 0; yy < 4; yy++)
        dst[(size_t)(nd0 + threadIdx.y + yy*8) * Ln + l0 + threadIdx.x] =
            tile[threadIdx.x][threadIdx.y + yy*8];
}

// Softmax over k with bias + mask; writes P as bf16 hi/lo
__global__ void k_softmax(const int* __restrict__ mask){
    int h = blockIdx.x >> 9, q = blockIdx.x & (Ln-1);
    const float* row = g_attn + ((size_t)h*Ln + q)*Ln;
    bool padq = (mask[q] == 0);
    int t = threadIdx.x;
    int k0 = t, k1 = t + 256;
    float v0 = (padq || mask[k0] == 0) ? -1e9f : row[k0] + g_bias[((size_t)q*Ln + k0)*Hh + h];
    float v1 = (padq || mask[k1] == 0) ? -1e9f : row[k1] + g_bias[((size_t)q*Ln + k1)*Hh + h];
    __shared__ float red[256];
    red[t] = fmaxf(v0, v1); __syncthreads();
    for (int s = 128; s > 0; s >>= 1){ if (t < s) red[t] = fmaxf(red[t], red[t+s]); __syncthreads(); }
    float m = red[0]; __syncthreads();
    float e0 = expf(v0 - m), e1 = expf(v1 - m);
    red[t] = e0 + e1; __syncthreads();
    for (int s = 128; s > 0; s >>= 1){ if (t < s) red[t] += red[t+s]; __syncthreads(); }
    float inv = 1.f / red[0];
    size_t base = ((size_t)h*Ln + q)*Ln;
    split_store(g_p_hi, g_p_lo, base + k0, e0*inv);
    split_store(g_p_hi, g_p_lo, base + k1, e1*inv);
}

// ----------------------------------------------------------------------------
// Warp-MMA GEMM. MODE: 0=QKVG, 1=attn logits, 2=AV, 3=out-proj
// D[BM=128, BN=64] = A[M,K] @ B[N,K]^T,  A/B bf16 hi/lo K-major.
// 8 warps: 4(M) x 2(N), each 32x32.  BK=32, double-buffered cp.async.
// SMEM row stride: 40 bf16 (80 B, 16B-aligned rows; i*20 words mod 32 distinct
// over 8 rows -> conflict-free ldmatrix).
#define RS   40
#define AELE 5120             // 128*40
#define BELE 2560             // 64*40
#define BUFE 15360            // Ah+Al+Bh+Bl elems per buffer
#define SMEMB (2*BUFE*2)      // 61440 bytes

template<int MODE>
__global__ __launch_bounds__(256, 2) void k_mma(const int* __restrict__ mask,
                                                const float* __restrict__ bg,
                                                const float* __restrict__ bout,
                                                float* __restrict__ outp){
    extern __shared__ bf16 smem[];
    uint32_t sb = s2u(smem);
    int tid = threadIdx.x, wid = tid >> 5, lid = tid & 31;
    int wm = wid & 3, wn = wid >> 2;
    int h = blockIdx.z;
    int m0 = blockIdx.y * 128, n0 = blockIdx.x * 64;
    const int K   = (MODE==1) ? NDIM : (MODE==2) ? Ln : 256;
    const int nit = K / 32;

    const bf16 *Ah, *Al, *Bh, *Bl; int lda = 0, ldb = 0;
    if (MODE == 0){
        Ah = g_bufA_hi; Al = g_bufA_lo; lda = 256;
        Bh = g_wt_hi;   Bl = g_wt_lo;   ldb = 256;
    } else if (MODE == 1){
        size_t o = (size_t)h * Ln * NDIM;
        Ah = g_bufB_hi + o; Al = g_bufB_lo + o; lda = NDIM;
        Bh = g_k_hi + o;    Bl = g_k_lo + o;    ldb = NDIM;
    } else if (MODE == 2){
        size_t oa = (size_t)h * Ln * Ln;
        Ah = g_p_hi + oa; Al = g_p_lo + oa; lda = Ln;
        size_t ob = (size_t)h * NDIM * Ln;
        Bh = g_bufA_hi + ob; Bl = g_bufA_lo + ob; ldb = Ln;
    } else {
        Ah = g_bufB_hi; Al = g_bufB_lo; lda = 0;
        Bh = g_wt_hi + 1024*256; Bl = g_wt_lo + 1024*256; ldb = 256;
    }

    float acc[2][4][4] = {};

    auto issue = [&](int it){
        int b = it & 1, kt = it * 32;
        #pragma unroll
        for (int t = 0; t < 2; t++){
            int q = tid + t*256;
            int r = q >> 2, cc = q & 3;
            uint32_t so = sb + 2*(b*BUFE + r*RS + cc*8);
            const bf16 *gh, *gl;
            if (MODE == 3){
                int row = m0 + r; int n = row >> 9, l = row & (Ln-1);
                int c0 = kt + cc*8; int hh = c0 >> 5, d0 = c0 & 31;
                size_t off = ((size_t)(hh*Ln + l))*NDIM + (n << 5) + d0;
                gh = Ah + off; gl = Al + off;
            } else {
                size_t off = (size_t)(m0 + r)*lda + kt + cc*8;
                gh = Ah + off; gl = Al + off;
            }
            CP16(so, gh);
            CP16(so + 2*AELE, gl);
        }
        {
            int r = tid >> 2, cc = tid & 3;
            uint32_t so = sb + 2*(b*BUFE + 2*AELE + r*RS + cc*8);
            size_t off = (size_t)(n0 + r)*ldb + kt + cc*8;
            CP16(so, Bh + off);
            CP16(so + 2*BELE, Bl + off);
        }
        CPCOMMIT();
    };

    issue(0);
    for (int it = 0; it < nit; it++){
        if (it + 1 < nit){ issue(it + 1); CPWAIT(1); }
        else             { CPWAIT(0); }
        __syncthreads();
        int b = it & 1;
        #pragma unroll
        for (int kk = 0; kk < 2; kk++){
            uint32_t ah[2][4], al[2][4], bh[2][4], bl[2][4];
            int lrow = lid & 15, lch = lid >> 4;
            #pragma unroll
            for (int mi = 0; mi < 2; mi++){
                uint32_t base = sb + 2*(b*BUFE + (wm*32 + mi*16 + lrow)*RS + kk*16 + lch*8);
                ldsm4(base, ah[mi]);
                ldsm4(base + 2*AELE, al[mi]);
            }
            #pragma unroll
            for (int nj = 0; nj < 2; nj++){
                uint32_t base = sb + 2*(b*BUFE + 2*AELE + (wn*32 + nj*16 + lrow)*RS + kk*16 + lch*8);
                ldsm4(base, bh[nj]);
                ldsm4(base + 2*BELE, bl[nj]);
            }
            #pragma unroll
            for (int mi = 0; mi < 2; mi++)
                #pragma unroll
                for (int ni = 0; ni < 4; ni++){
                    int nj = ni >> 1, sel = ni & 1;
                    mma16816(acc[mi][ni], ah[mi], bh[nj][sel], bh[nj][2+sel]);
                    mma16816(acc[mi][ni], ah[mi], bl[nj][sel], bl[nj][2+sel]);
                    mma16816(acc[mi][ni], al[mi], bh[nj][sel], bh[nj][2+sel]);
                }
        }
        __syncthreads();
    }

    // epilogue
    int lr = lid >> 2, lc = (lid & 3)*2;
    #pragma unroll
    for (int mi = 0; mi < 2; mi++){
        #pragma unroll
        for (int ni = 0; ni < 4; ni++){
            #pragma unroll
            for (int e = 0; e < 4; e++){
                int row = m0 + wm*32 + mi*16 + lr + (e >= 2 ? 8 : 0);
                int gcol = n0 + wn*32 + ni*8 + lc + (e & 1);
                float val = acc[mi][ni][e];
                if (MODE == 0){
                    int z = gcol >> 8, j = gcol & 255;
                    int l = row & (Ln-1), n = row >> 9;
                    bool pad = (mask[l] == 0);
                    if (z == 3){
                        g_gate[(size_t)row*HD + j] = 1.f/(1.f + expf(-(val + bg[j])));
                    } else {
                        float v2 = pad ? 0.f : (z == 1 ? val*SCALING : val);
                        int hh = j >> 5, d = j & 31;
                        size_t idx = ((size_t)(hh*Ln + l))*NDIM + (n << 5) + d;
                        if (z == 0)      split_store(g_bufB_hi, g_bufB_lo, idx, v2);
                        else if (z == 1) split_store(g_k_hi, g_k_lo, idx, v2);
                        else             split_store(g_v_hi, g_v_lo, idx, v2);
                    }
                } else if (MODE == 1){
                    g_attn[((size_t)(h*Ln + row))*Ln + gcol] = val;
                } else if (MODE == 2){
                    int n = gcol >> 5, d = gcol & 31;
                    float gt = g_gate[((size_t)(n*Ln + row))*HD + h*32 + d];
                    split_store(g_bufB_hi, g_bufB_lo, ((size_t)(h*Ln + row))*NDIM + gcol, val*gt);
                } else {
                    int l = row & (Ln-1);
                    bool pad = (mask[l] == 0);
                    outp[(size_t)row*HD + gcol] = pad ? 0.f : (val + bout[gcol]);
                }
            }
        }
    }
}

// ----------------------------------------------------------------------------
extern "C" void kernel_launch(void* const* d_in, const int* in_sizes, int n_in,
                              void* d_out, int out_size){
    const float* msa      = (const float*)d_in[0];
    const float* pair     = (const float*)d_in[1];
    const float* ln_msa_g = (const float*)d_in[2];
    const float* ln_msa_b = (const float*)d_in[3];
    const float* ln_pr_g  = (const float*)d_in[4];
    const float* ln_pr_b  = (const float*)d_in[5];
    const float* w_q      = (const float*)d_in[6];
    const float* w_k      = (const float*)d_in[7];
    const float* w_v      = (const float*)d_in[8];
    const float* w_b      = (const float*)d_in[9];
    const float* w_g      = (const float*)d_in[10];
    const float* b_g      = (const float*)d_in[11];
    const float* w_out    = (const float*)d_in[12];
    const float* b_out    = (const float*)d_in[13];
    const int*   mask     = (const int*)  d_in[14];
    float* out = (float*)d_out;

    cudaFuncSetAttribute(k_mma<0>, cudaFuncAttributeMaxDynamicSharedMemorySize, SMEMB);
    cudaFuncSetAttribute(k_mma<1>, cudaFuncAttributeMaxDynamicSharedMemorySize, SMEMB);
    cudaFuncSetAttribute(k_mma<2>, cudaFuncAttributeMaxDynamicSharedMemorySize, SMEMB);
    cudaFuncSetAttribute(k_mma<3>, cudaFuncAttributeMaxDynamicSharedMemorySize, SMEMB);

    k_ln_msa   <<<NL/8, 256>>>(msa, ln_msa_g, ln_msa_b);
    k_conv_w   <<<1280, 256>>>(w_q, w_k, w_v, w_g, w_out);
    k_pair_bias<<<(Ln*Ln)/8, 256>>>(pair, ln_pr_g, ln_pr_b, w_b);
    k_mma<0>   <<<dim3(16, 1024, 1), 256, SMEMB>>>(mask, b_g, b_out, out);
    k_transpose_v<<<dim3(NDIM/32, Ln/32, 16), dim3(32, 8)>>>();
    k_mma<1>   <<<dim3(8, 4, 8),    256, SMEMB>>>(mask, b_g, b_out, out);
    k_softmax  <<<Hh*Ln, 256>>>(mask);
    k_mma<2>   <<<dim3(128, 4, 8),  256, SMEMB>>>(mask, b_g, b_out, out);
    k_mma<3>   <<<dim3(4, 1024, 1), 256, SMEMB>>>(mask, b_g, b_out, out);
}